// round 6
// baseline (speedup 1.0000x reference)
#include <cuda_runtime.h>
#include <math.h>
#include <stdint.h>

#define N 8192
#define D 64
#define H1 128
#define H2 64
#define KNB 16            // kept neighbors per row (rank 0 = self, dropped)
#define E (N * KNB)       // 131072 fixed edge slots, src(e) = e >> 4
#define CAP 512           // candidate slots per row
#define CAND_THR 0.25f    // prefilter threshold (17th max ~ 0.36 for this data)

// ---------------- device scratch (no allocations allowed) ----------------
__device__ unsigned long long g_cand[(size_t)N * CAP];  // 32 MB candidate keys
__device__ int   g_ccnt[N];
__device__ int   g_bad[N];
__device__ float g_ninv[N];                // 1/||x_i||
__device__ float g_dinv[N];
__device__ int   g_edst[E];
__device__ float g_ew[E];
__device__ int   g_cnt[N];
__device__ int   g_fill[N];
__device__ int   g_off[N + 1];
__device__ int   g_inc[E];                 // CSR-by-dst edge ids (sorted per bucket)
__device__ float g_h1[(size_t)N * H1];
__device__ float g_y1[(size_t)N * H1];
__device__ float g_h2[(size_t)N * H2];
__device__ float g_y2[(size_t)N * H2];

// order-preserving float <-> uint key (ascending)
__device__ __forceinline__ unsigned okey(float v) {
    unsigned u = __float_as_uint(v);
    return u ^ (((unsigned)((int)u >> 31)) | 0x80000000u);
}
__device__ __forceinline__ float iokey(unsigned u) {
    return __uint_as_float(u ^ ((~((unsigned)((int)u >> 31))) | 0x80000000u));
}

#define FFMA2(acc, pa, pb) \
    asm("fma.rn.f32x2 %0, %1, %2, %0;" : "+l"(acc) : "l"(pa), "l"(pb))
#define PACK2(dst, a) \
    asm("mov.b64 %0, {%1, %1};" : "=l"(dst) : "r"(__float_as_uint(a)))
#define UNPACK2(lo, hi, src) \
    asm("mov.b64 {%0, %1}, %2;" : "=r"(lo), "=r"(hi) : "l"(src))

// ---------------- fused norms + init ----------------
__global__ void norm_init_kernel(const float* __restrict__ x,
                                 float* o_ei0, float* o_ei1, float* o_ew) {
    int gi = blockIdx.x * blockDim.x + threadIdx.x;
    if (gi < N) {
        g_ccnt[gi] = 0;
        g_bad[gi]  = 0;
        g_cnt[gi]  = 0;
        g_fill[gi] = 0;
        if (o_ei0) {
            size_t p = (size_t)E + gi;
            o_ei0[p] = (float)gi;
            o_ei1[p] = (float)gi;
            o_ew[p]  = 1.0f;
        }
    }
    int warp = gi >> 5;
    int lane = threadIdx.x & 31;
    if (warp >= N) return;
    const float* row = x + (size_t)warp * D;
    float a = row[lane], b = row[lane + 32];
    float s = a * a + b * b;
#pragma unroll
    for (int o = 16; o; o >>= 1) s += __shfl_xor_sync(0xffffffffu, s, o);
    if (lane == 0) g_ninv[warp] = 1.0f / sqrtf(s);
}

__device__ __forceinline__ void push_cand(int r, int c, float v) {
    int slot = atomicAdd(&g_ccnt[r], 1);
    if (slot < CAP)
        g_cand[(size_t)r * CAP + slot] =
            ((unsigned long long)okey(v) << 32) | (unsigned)(~(unsigned)c);
}

// ---------------- similarity GEMM (symmetric, packed f32x2) + candidate filter --------
// 128x64 tile, 256 threads, 8x4 micro-tile. Tiles with bj >= 2*bi computed
// (upper triangle); partial (diagonal-straddling) tiles guard cc >= rr.
// a comes from transposed smem (LDS.128 x2), b as natural u64 col-pairs (no pack).
__global__ __launch_bounds__(256, 3) void sim_kernel(const float* __restrict__ x) {
    const int bi = blockIdx.y, bj = blockIdx.x;
    if (bj < 2 * bi) return;
    __shared__ float As[64][128];   // As[d][r], 32KB
    __shared__ float Bs[64][64];    // Bs[d][c], 16KB
    const int tid = threadIdx.x;
    const int tx = tid & 15, ty = tid >> 4;
    const int br = bi << 7, bc = bj << 6;

    // conflict-free transposed stores: consecutive lanes cover consecutive rows
    for (int i = tid; i < 2048; i += 256) {
        int r = i & 127, d0 = (i >> 7) << 2;
        float4 v = *(const float4*)&x[(size_t)(br + r) * D + d0];
        As[d0 + 0][r] = v.x; As[d0 + 1][r] = v.y;
        As[d0 + 2][r] = v.z; As[d0 + 3][r] = v.w;
    }
    for (int i = tid; i < 1024; i += 256) {
        int c = i & 63, d0 = (i >> 6) << 2;
        float4 v = *(const float4*)&x[(size_t)(bc + c) * D + d0];
        Bs[d0 + 0][c] = v.x; Bs[d0 + 1][c] = v.y;
        Bs[d0 + 2][c] = v.z; Bs[d0 + 3][c] = v.w;
    }
    __syncthreads();

    unsigned long long acc[8][2];
#pragma unroll
    for (int i = 0; i < 8; i++) { acc[i][0] = 0ull; acc[i][1] = 0ull; }

#pragma unroll 8
    for (int d = 0; d < 64; d++) {
        float4 a0 = *(const float4*)&As[d][ty * 8];
        float4 a1 = *(const float4*)&As[d][ty * 8 + 4];
        ulonglong2 bb = *(const ulonglong2*)&Bs[d][tx * 4];
        unsigned long long p[8];
        PACK2(p[0], a0.x); PACK2(p[1], a0.y); PACK2(p[2], a0.z); PACK2(p[3], a0.w);
        PACK2(p[4], a1.x); PACK2(p[5], a1.y); PACK2(p[6], a1.z); PACK2(p[7], a1.w);
#pragma unroll
        for (int i = 0; i < 8; i++) {
            FFMA2(acc[i][0], p[i], bb.x);
            FFMA2(acc[i][1], p[i], bb.y);
        }
    }

    float irv[8], icv[4];
#pragma unroll
    for (int i = 0; i < 8; i++) irv[i] = g_ninv[br + ty * 8 + i];
#pragma unroll
    for (int j = 0; j < 4; j++) icv[j] = g_ninv[bc + tx * 4 + j];

    const bool part = ((bj >> 1) == bi);   // diagonal-straddling tile
#pragma unroll
    for (int i = 0; i < 8; i++) {
        unsigned u[4];
        UNPACK2(u[0], u[1], acc[i][0]);
        UNPACK2(u[2], u[3], acc[i][1]);
        int rr = br + ty * 8 + i;
#pragma unroll
        for (int j = 0; j < 4; j++) {
            float v = __uint_as_float(u[j]) * irv[i] * icv[j];
            int cc = bc + tx * 4 + j;
            if (v > CAND_THR && (!part || cc >= rr)) {
                push_cand(rr, cc, v);
                if (cc != rr) push_cand(cc, rr, v);
            }
        }
    }
}

// ---------------- top-17 from candidate buckets: one warp per row ----------------
// Incremental: per-lane running best; per round only the unique winning lane
// rescans. Repeated max over a set is order-invariant -> deterministic.
__global__ void topk_cand_kernel(float* o_ei0, float* o_ei1, float* o_ew) {
    const int warp = threadIdx.x >> 5;
    const int lane = threadIdx.x & 31;
    const int r = blockIdx.x * 8 + warp;
    int cnt = g_ccnt[r];
    if (cnt < 17 || cnt > CAP) {
        if (lane == 0) g_bad[r] = 1;   // fallback recomputes this row
        return;
    }
    const unsigned long long* base = g_cand + (size_t)r * CAP;
    unsigned long long k[16];
#pragma unroll
    for (int j = 0; j < 16; j++) {
        int idx = lane + (j << 5);
        k[j] = (idx < cnt) ? base[idx] : 0ull;
    }
    unsigned long long best = k[0];
#pragma unroll
    for (int j = 1; j < 16; j++) if (k[j] > best) best = k[j];

    unsigned long long mine = 0ull;
    for (int t = 0; t < 17; t++) {
        unsigned long long m = best;
#pragma unroll
        for (int off = 16; off; off >>= 1) {
            unsigned long long o = __shfl_xor_sync(0xffffffffu, m, off);
            if (o > m) m = o;
        }
        if (t == lane + 1) mine = m;      // lane l keeps rank l+1
        if (best == m) {                  // unique winner (keys embed idx)
#pragma unroll
            for (int j = 0; j < 16; j++) if (k[j] == m) k[j] = 0ull;
            best = k[0];
#pragma unroll
            for (int j = 1; j < 16; j++) if (k[j] > best) best = k[j];
        }
    }
    if (lane < 16) {
        unsigned idx = ~((unsigned)mine);
        float val = iokey((unsigned)(mine >> 32));
        float w = (val > 0.5f) ? val : 0.0f;
        int e = r * KNB + lane;
        g_edst[e] = (int)idx;
        g_ew[e]   = w;
        if (o_ei0) {
            o_ei0[e] = (float)r;
            o_ei1[e] = (float)idx;
            o_ew[e]  = w;
        }
    }
}

// ---------------- fallback: full-row recompute for flagged rows (normally none) -------
__global__ void fallback_kernel(const float* __restrict__ x,
                                float* o_ei0, float* o_ei1, float* o_ew) {
    __shared__ float xr[64];
    __shared__ float snv;
    __shared__ unsigned long long keys[256];
    __shared__ unsigned long long wins[17];
    const int t = threadIdx.x;
    for (int r = blockIdx.x; r < N; r += gridDim.x) {
        if (g_bad[r] == 0) continue;
        if (t < 64) xr[t] = x[(size_t)r * D + t];
        if (t == 0) snv = g_ninv[r];
        __syncthreads();

        unsigned long long k[32];
#pragma unroll 1
        for (int j = 0; j < 32; j++) {
            int c = t + (j << 8);
            const float* xc = x + (size_t)c * D;
            float dot = 0.0f;
            for (int d = 0; d < 64; d++) dot = fmaf(xc[d], xr[d], dot);
            float v = dot * snv * g_ninv[c];
            k[j] = ((unsigned long long)okey(v) << 32) | (unsigned)(~(unsigned)c);
        }
        unsigned long long m = k[0];
#pragma unroll
        for (int j = 1; j < 32; j++) if (k[j] > m) m = k[j];
        keys[t] = m;
        __syncthreads();

        for (int kk = 0; kk < 17; kk++) {
            if (t < 32) {
                unsigned long long mm = keys[t];
#pragma unroll
                for (int w = 1; w < 8; w++) {
                    unsigned long long o = keys[t + (w << 5)];
                    if (o > mm) mm = o;
                }
#pragma unroll
                for (int off = 16; off; off >>= 1) {
                    unsigned long long o = __shfl_xor_sync(0xffffffffu, mm, off);
                    if (o > mm) mm = o;
                }
                if (t == 0) wins[kk] = mm;
            }
            __syncthreads();
            unsigned long long wk = wins[kk];
            unsigned widx = ~((unsigned)wk);
            if ((int)(widx & 255) == t) {
#pragma unroll
                for (int j = 0; j < 32; j++) if (k[j] == wk) k[j] = 0ull;
                unsigned long long mm = k[0];
#pragma unroll
                for (int j = 1; j < 32; j++) if (k[j] > mm) mm = k[j];
                keys[t] = mm;
            }
            __syncthreads();
        }

        if (t >= 1 && t < 17) {
            unsigned long long wk = wins[t];
            unsigned idx = ~((unsigned)wk);
            float val = iokey((unsigned)(wk >> 32));
            float w = (val > 0.5f) ? val : 0.0f;
            int e = r * KNB + (t - 1);
            g_edst[e] = (int)idx;
            g_ew[e]   = w;
            if (o_ei0) {
                o_ei0[e] = (float)r;
                o_ei1[e] = (float)idx;
                o_ew[e]  = w;
            }
        }
        __syncthreads();
    }
}

// ---------------- CSR-by-dst build (deterministic) ------------
__global__ void count_kernel() {
    int e = blockIdx.x * blockDim.x + threadIdx.x;
    if (e < E && g_ew[e] > 0.0f) atomicAdd(&g_cnt[g_edst[e]], 1);
}

__global__ void scan_kernel() {   // 1 block, 1024 threads, 8 elems each
    __shared__ int ss[1024];
    int t = threadIdx.x;
    int base = t * 8;
    int loc[8];
    int s = 0;
#pragma unroll
    for (int j = 0; j < 8; j++) { loc[j] = s; s += g_cnt[base + j]; }
    ss[t] = s;
    __syncthreads();
    for (int d = 1; d < 1024; d <<= 1) {
        int v = (t >= d) ? ss[t - d] : 0;
        __syncthreads();
        ss[t] += v;
        __syncthreads();
    }
    int excl = (t == 0) ? 0 : ss[t - 1];
#pragma unroll
    for (int j = 0; j < 8; j++) g_off[base + j] = excl + loc[j];
    if (t == 1023) g_off[N] = ss[1023];
}

__global__ void fill_kernel() {
    int e = blockIdx.x * blockDim.x + threadIdx.x;
    if (e < E && g_ew[e] > 0.0f) {
        int d = g_edst[e];
        int slot = atomicAdd(&g_fill[d], 1);
        g_inc[g_off[d] + slot] = e;
    }
}

// sort each bucket by edge id (canonical order), then deterministic deg
__global__ void sortdeg_kernel() {
    int d = blockIdx.x * blockDim.x + threadIdx.x;
    if (d >= N) return;
    int s = g_off[d], e = g_off[d + 1];
    for (int i = s + 1; i < e; i++) {
        int key = g_inc[i];
        int j = i - 1;
        while (j >= s && g_inc[j] > key) { g_inc[j + 1] = g_inc[j]; j--; }
        g_inc[j + 1] = key;
    }
    float deg = 2.0f;   // graph self-loop (w=1) + gcn self-loop (w=1)
    for (int i = s; i < e; i++) deg += g_ew[g_inc[i]];
    g_dinv[d] = 1.0f / sqrtf(deg);
}

// ---------------- small dense GEMM: C[N][FOUT] = A[N][FIN] @ W (+bias) ----------------
template <int FIN, int FOUT, int NB>
__global__ void gemm_kernel(const float* __restrict__ A, const float* __restrict__ W,
                            const float* __restrict__ bias, float* __restrict__ C) {
    __shared__ float As[NB][FIN];
    __shared__ float Ws[FIN * FOUT];
    const int t = threadIdx.x;        // FOUT threads
    const int n0 = blockIdx.x * NB;
    for (int i = t; i < NB * FIN; i += FOUT) As[i / FIN][i % FIN] = A[(size_t)n0 * FIN + i];
    for (int i = t; i < FIN * FOUT; i += FOUT) Ws[i] = W[i];
    __syncthreads();
#pragma unroll 1
    for (int n = 0; n < NB; n++) {
        float acc = bias ? bias[t] : 0.0f;
#pragma unroll
        for (int d = 0; d < FIN; d++) acc = fmaf(As[n][d], Ws[d * FOUT + t], acc);
        C[(size_t)(n0 + n) * FOUT + t] = acc;
    }
}

// ---------------- fused gather + bias + relu + LayerNorm (deterministic) ----------
template <int F>
__global__ void gather_epi_kernel(const float* __restrict__ h, const float* __restrict__ b,
                                  const float* __restrict__ g, const float* __restrict__ be,
                                  float* __restrict__ y) {
    const int n = blockIdx.x;
    const int f = threadIdx.x;
    __shared__ float s1[F / 32];
    __shared__ float s2[F / 32];

    int s = g_off[n], e = g_off[n + 1];
    float di = g_dinv[n];
    float acc = 0.0f;
    for (int i = s; i < e; i++) {
        int eid = g_inc[i];
        int src = eid >> 4;
        acc = fmaf(g_ew[eid] * g_dinv[src], h[(size_t)src * F + f], acc);
    }
    float v = acc * di + 2.0f * di * di * h[(size_t)n * F + f] + b[f];
    v = fmaxf(v, 0.0f);

    float sv = v;
#pragma unroll
    for (int o = 16; o; o >>= 1) sv += __shfl_xor_sync(0xffffffffu, sv, o);
    if ((f & 31) == 0) s1[f >> 5] = sv;
    __syncthreads();
    float tot = 0.0f;
#pragma unroll
    for (int i = 0; i < F / 32; i++) tot += s1[i];
    float mu = tot / (float)F;

    float dv = v - mu;
    float sq = dv * dv;
#pragma unroll
    for (int o = 16; o; o >>= 1) sq += __shfl_xor_sync(0xffffffffu, sq, o);
    if ((f & 31) == 0) s2[f >> 5] = sq;
    __syncthreads();
    float tot2 = 0.0f;
#pragma unroll
    for (int i = 0; i < F / 32; i++) tot2 += s2[i];
    float var = tot2 / (float)F;

    y[(size_t)n * F + f] = dv * (1.0f / sqrtf(var + 1e-5f)) * g[f] + be[f];
}

// ---------------- launch ----------------
extern "C" void kernel_launch(void* const* d_in, const int* in_sizes, int n_in,
                              void* d_out, int out_size) {
    const float* x   = (const float*)d_in[0];
    const float* W1  = (const float*)d_in[1];
    const float* b1  = (const float*)d_in[2];
    const float* g1  = (const float*)d_in[3];
    const float* be1 = (const float*)d_in[4];
    const float* W2  = (const float*)d_in[5];
    const float* b2  = (const float*)d_in[6];
    const float* g2  = (const float*)d_in[7];
    const float* be2 = (const float*)d_in[8];
    const float* Wp  = (const float*)d_in[9];
    const float* bp  = (const float*)d_in[10];

    float* o = (float*)d_out;
    const int OUT_ELEMS = N * D;                  // 524288
    const int E_TOTAL = E + N;                    // 139264
    const int FULL = OUT_ELEMS + 3 * E_TOTAL;     // 942080

    float* o_out = nullptr;
    float* o_ei0 = nullptr;
    float* o_ei1 = nullptr;
    float* o_ew  = nullptr;
    if (out_size >= OUT_ELEMS) o_out = o;
    if (out_size >= FULL) {
        o_ei0 = o + OUT_ELEMS;
        o_ei1 = o_ei0 + E_TOTAL;
        o_ew  = o_ei1 + E_TOTAL;
    }

    norm_init_kernel<<<(N * 32) / 256, 256>>>(x, o_ei0, o_ei1, o_ew);
    sim_kernel<<<dim3(N / 64, N / 128), 256>>>(x);
    topk_cand_kernel<<<N / 8, 256>>>(o_ei0, o_ei1, o_ew);
    fallback_kernel<<<128, 256>>>(x, o_ei0, o_ei1, o_ew);

    count_kernel<<<E / 256, 256>>>();
    scan_kernel<<<1, 1024>>>();
    fill_kernel<<<E / 256, 256>>>();
    sortdeg_kernel<<<(N + 255) / 256, 256>>>();

    // layer 1
    gemm_kernel<D, H1, 16><<<N / 16, H1>>>(x, W1, nullptr, g_h1);
    gather_epi_kernel<H1><<<N, H1>>>(g_h1, b1, g1, be1, g_y1);

    // layer 2
    gemm_kernel<H1, H2, 16><<<N / 16, H2>>>(g_y1, W2, nullptr, g_h2);
    gather_epi_kernel<H2><<<N, H2>>>(g_h2, b2, g2, be2, g_y2);

    // projection (+bias) straight into output
    if (o_out)
        gemm_kernel<H2, D, 16><<<N / 16, D>>>(g_y2, Wp, bp, o_out);
}

// round 7
// speedup vs baseline: 1.1701x; 1.1701x over previous
#include <cuda_runtime.h>
#include <math.h>
#include <stdint.h>

#define N 8192
#define D 64
#define H1 128
#define H2 64
#define KNB 16            // kept neighbors per row (rank 0 = self, dropped)
#define E (N * KNB)       // 131072 fixed edge slots, src(e) = e >> 4
#define CAP 512           // candidate slots per row
#define CAND_THR 0.25f    // prefilter threshold (17th max ~ 0.36 for this data)

// ---------------- device scratch (no allocations allowed) ----------------
__device__ unsigned long long g_cand[(size_t)N * CAP];  // 32 MB candidate keys
__device__ int   g_ccnt[N];
__device__ int   g_bad[N];
__device__ float g_ninv[N];                // 1/||x_i||
__device__ float g_dinv[N];
__device__ int   g_edst[E];
__device__ float g_ew[E];
__device__ int   g_cnt[N];
__device__ int   g_fill[N];
__device__ int   g_off[N + 1];
__device__ int   g_inc[E];                 // CSR-by-dst edge ids (sorted per bucket)
__device__ float g_h1[(size_t)N * H1];
__device__ float g_y1[(size_t)N * H1];
__device__ float g_h2[(size_t)N * H2];
__device__ float g_y2[(size_t)N * H2];

// order-preserving float <-> uint key (ascending)
__device__ __forceinline__ unsigned okey(float v) {
    unsigned u = __float_as_uint(v);
    return u ^ (((unsigned)((int)u >> 31)) | 0x80000000u);
}
__device__ __forceinline__ float iokey(unsigned u) {
    return __uint_as_float(u ^ ((~((unsigned)((int)u >> 31))) | 0x80000000u));
}

#define FFMA2(acc, pa, pb) \
    asm("fma.rn.f32x2 %0, %1, %2, %0;" : "+l"(acc) : "l"(pa), "l"(pb))
#define PACK2(dst, a) \
    asm("mov.b64 %0, {%1, %1};" : "=l"(dst) : "r"(__float_as_uint(a)))
#define UNPACK2(lo, hi, src) \
    asm("mov.b64 {%0, %1}, %2;" : "=r"(lo), "=r"(hi) : "l"(src))

// ---------------- fused norms + init ----------------
__global__ void norm_init_kernel(const float* __restrict__ x,
                                 float* o_ei0, float* o_ei1, float* o_ew) {
    int gi = blockIdx.x * blockDim.x + threadIdx.x;
    if (gi < N) {
        g_ccnt[gi] = 0;
        g_bad[gi]  = 0;
        g_cnt[gi]  = 0;
        g_fill[gi] = 0;
        if (o_ei0) {
            size_t p = (size_t)E + gi;
            o_ei0[p] = (float)gi;
            o_ei1[p] = (float)gi;
            o_ew[p]  = 1.0f;
        }
    }
    int warp = gi >> 5;
    int lane = threadIdx.x & 31;
    if (warp >= N) return;
    const float* row = x + (size_t)warp * D;
    float a = row[lane], b = row[lane + 32];
    float s = a * a + b * b;
#pragma unroll
    for (int o = 16; o; o >>= 1) s += __shfl_xor_sync(0xffffffffu, s, o);
    if (lane == 0) g_ninv[warp] = 1.0f / sqrtf(s);
}

__device__ __forceinline__ void push_cand(int r, int c, float v) {
    int slot = atomicAdd(&g_ccnt[r], 1);
    if (slot < CAP)
        g_cand[(size_t)r * CAP + slot] =
            ((unsigned long long)okey(v) << 32) | (unsigned)(~(unsigned)c);
}

// ---------------- similarity GEMM (symmetric, packed f32x2) + candidate filter --------
// 64x64 tile, 256 threads, 4x4 micro-tile (R5 tiling — measured fastest).
// Only bj >= bi computed; candidates pushed to both rows.
__global__ void sim_kernel(const float* __restrict__ x) {
    const int bi = blockIdx.y, bj = blockIdx.x;
    if (bj < bi) return;
    __shared__ float As[64][65];   // As[r][d]
    __shared__ float Bt[64][68];   // Bt[d][c]
    const int tid = threadIdx.x;
    const int tx = tid & 15, ty = tid >> 4;
    const int br = bi << 6, bc = bj << 6;

    for (int i = tid; i < 4096; i += 256) {
        int r = i >> 6, d = i & 63;
        As[r][d] = x[(size_t)(br + r) * D + d];
        Bt[d][r] = x[(size_t)(bc + r) * D + d];
    }
    __syncthreads();

    unsigned long long acc[4][2];
#pragma unroll
    for (int i = 0; i < 4; i++) { acc[i][0] = 0ull; acc[i][1] = 0ull; }

#pragma unroll 16
    for (int d = 0; d < 64; d++) {
        float a0 = As[ty * 4 + 0][d];
        float a1 = As[ty * 4 + 1][d];
        float a2 = As[ty * 4 + 2][d];
        float a3 = As[ty * 4 + 3][d];
        ulonglong2 bb = *(const ulonglong2*)&Bt[d][tx * 4];
        unsigned long long p0, p1, p2, p3;
        PACK2(p0, a0); PACK2(p1, a1); PACK2(p2, a2); PACK2(p3, a3);
        FFMA2(acc[0][0], p0, bb.x); FFMA2(acc[0][1], p0, bb.y);
        FFMA2(acc[1][0], p1, bb.x); FFMA2(acc[1][1], p1, bb.y);
        FFMA2(acc[2][0], p2, bb.x); FFMA2(acc[2][1], p2, bb.y);
        FFMA2(acc[3][0], p3, bb.x); FFMA2(acc[3][1], p3, bb.y);
    }

    float ic[4], ir[4];
#pragma unroll
    for (int j = 0; j < 4; j++) ic[j] = g_ninv[bc + tx * 4 + j];
#pragma unroll
    for (int i = 0; i < 4; i++) ir[i] = g_ninv[br + ty * 4 + i];

#pragma unroll
    for (int i = 0; i < 4; i++) {
        unsigned u[4];
        UNPACK2(u[0], u[1], acc[i][0]);
        UNPACK2(u[2], u[3], acc[i][1]);
#pragma unroll
        for (int j = 0; j < 4; j++) {
            float v = __uint_as_float(u[j]) * ir[i] * ic[j];
            if (v > CAND_THR) {
                int r = br + ty * 4 + i;
                int c = bc + tx * 4 + j;
                push_cand(r, c, v);
                if (bi != bj) push_cand(c, r, v);
            }
        }
    }
}

// ---------------- top-17 from candidate buckets: one warp per row ----------------
// Incremental: per-lane running best; per round only the unique winning lane
// rescans. Repeated max over a set is order-invariant -> deterministic.
// Also counts CSR in-degree (integer atomics, deterministic values).
__global__ void topk_cand_kernel(float* o_ei0, float* o_ei1, float* o_ew) {
    const int warp = threadIdx.x >> 5;
    const int lane = threadIdx.x & 31;
    const int r = blockIdx.x * 8 + warp;
    int cnt = g_ccnt[r];
    if (cnt < 17 || cnt > CAP) {
        if (lane == 0) g_bad[r] = 1;   // fallback recomputes this row
        return;
    }
    const unsigned long long* base = g_cand + (size_t)r * CAP;
    unsigned long long k[16];
#pragma unroll
    for (int j = 0; j < 16; j++) {
        int idx = lane + (j << 5);
        k[j] = (idx < cnt) ? base[idx] : 0ull;
    }
    unsigned long long best = k[0];
#pragma unroll
    for (int j = 1; j < 16; j++) if (k[j] > best) best = k[j];

    unsigned long long mine = 0ull;
    for (int t = 0; t < 17; t++) {
        unsigned long long m = best;
#pragma unroll
        for (int off = 16; off; off >>= 1) {
            unsigned long long o = __shfl_xor_sync(0xffffffffu, m, off);
            if (o > m) m = o;
        }
        if (t == lane + 1) mine = m;      // lane l keeps rank l+1
        if (best == m) {                  // unique winner (keys embed idx)
#pragma unroll
            for (int j = 0; j < 16; j++) if (k[j] == m) k[j] = 0ull;
            best = k[0];
#pragma unroll
            for (int j = 1; j < 16; j++) if (k[j] > best) best = k[j];
        }
    }
    if (lane < 16) {
        unsigned idx = ~((unsigned)mine);
        float val = iokey((unsigned)(mine >> 32));
        float w = (val > 0.5f) ? val : 0.0f;
        int e = r * KNB + lane;
        g_edst[e] = (int)idx;
        g_ew[e]   = w;
        if (w > 0.0f) atomicAdd(&g_cnt[(int)idx], 1);
        if (o_ei0) {
            o_ei0[e] = (float)r;
            o_ei1[e] = (float)idx;
            o_ew[e]  = w;
        }
    }
}

// ---------------- fallback: full-row recompute for flagged rows (normally none) -------
// Each block owns 64 contiguous rows; parallel flag read + early exit (~2us).
__global__ void fallback_kernel(const float* __restrict__ x,
                                float* o_ei0, float* o_ei1, float* o_ew) {
    __shared__ float xr[64];
    __shared__ float snv;
    __shared__ unsigned long long keys[256];
    __shared__ unsigned long long wins[17];
    const int t = threadIdx.x;
    const int r0 = blockIdx.x * 64;

    int flag = (t < 64) ? g_bad[r0 + t] : 0;
    if (__syncthreads_or(flag) == 0) return;

    for (int rr = 0; rr < 64; rr++) {
        int r = r0 + rr;
        if (g_bad[r] == 0) continue;
        if (t < 64) xr[t] = x[(size_t)r * D + t];
        if (t == 0) snv = g_ninv[r];
        __syncthreads();

        unsigned long long k[32];
#pragma unroll 1
        for (int j = 0; j < 32; j++) {
            int c = t + (j << 8);
            const float* xc = x + (size_t)c * D;
            float dot = 0.0f;
            for (int d = 0; d < 64; d++) dot = fmaf(xc[d], xr[d], dot);
            float v = dot * snv * g_ninv[c];
            k[j] = ((unsigned long long)okey(v) << 32) | (unsigned)(~(unsigned)c);
        }
        unsigned long long m = k[0];
#pragma unroll
        for (int j = 1; j < 32; j++) if (k[j] > m) m = k[j];
        keys[t] = m;
        __syncthreads();

        for (int kk = 0; kk < 17; kk++) {
            if (t < 32) {
                unsigned long long mm = keys[t];
#pragma unroll
                for (int w = 1; w < 8; w++) {
                    unsigned long long o = keys[t + (w << 5)];
                    if (o > mm) mm = o;
                }
#pragma unroll
                for (int off = 16; off; off >>= 1) {
                    unsigned long long o = __shfl_xor_sync(0xffffffffu, mm, off);
                    if (o > mm) mm = o;
                }
                if (t == 0) wins[kk] = mm;
            }
            __syncthreads();
            unsigned long long wk = wins[kk];
            unsigned widx = ~((unsigned)wk);
            if ((int)(widx & 255) == t) {
#pragma unroll
                for (int j = 0; j < 32; j++) if (k[j] == wk) k[j] = 0ull;
                unsigned long long mm = k[0];
#pragma unroll
                for (int j = 1; j < 32; j++) if (k[j] > mm) mm = k[j];
                keys[t] = mm;
            }
            __syncthreads();
        }

        if (t >= 1 && t < 17) {
            unsigned long long wk = wins[t];
            unsigned idx = ~((unsigned)wk);
            float val = iokey((unsigned)(wk >> 32));
            float w = (val > 0.5f) ? val : 0.0f;
            int e = r * KNB + (t - 1);
            g_edst[e] = (int)idx;
            g_ew[e]   = w;
            if (w > 0.0f) atomicAdd(&g_cnt[(int)idx], 1);
            if (o_ei0) {
                o_ei0[e] = (float)r;
                o_ei1[e] = (float)idx;
                o_ew[e]  = w;
            }
        }
        __syncthreads();
    }
}

// ---------------- CSR-by-dst build (deterministic) ------------
__global__ void scan_kernel() {   // 1 block, 1024 threads, 8 elems each
    __shared__ int ss[1024];
    int t = threadIdx.x;
    int base = t * 8;
    int loc[8];
    int s = 0;
#pragma unroll
    for (int j = 0; j < 8; j++) { loc[j] = s; s += g_cnt[base + j]; }
    ss[t] = s;
    __syncthreads();
    for (int d = 1; d < 1024; d <<= 1) {
        int v = (t >= d) ? ss[t - d] : 0;
        __syncthreads();
        ss[t] += v;
        __syncthreads();
    }
    int excl = (t == 0) ? 0 : ss[t - 1];
#pragma unroll
    for (int j = 0; j < 8; j++) g_off[base + j] = excl + loc[j];
    if (t == 1023) g_off[N] = ss[1023];
}

__global__ void fill_kernel() {
    int e = blockIdx.x * blockDim.x + threadIdx.x;
    if (e < E && g_ew[e] > 0.0f) {
        int d = g_edst[e];
        int slot = atomicAdd(&g_fill[d], 1);
        g_inc[g_off[d] + slot] = e;
    }
}

// sort each bucket by edge id (canonical order), then deterministic deg
__global__ void sortdeg_kernel() {
    int d = blockIdx.x * blockDim.x + threadIdx.x;
    if (d >= N) return;
    int s = g_off[d], e = g_off[d + 1];
    for (int i = s + 1; i < e; i++) {
        int key = g_inc[i];
        int j = i - 1;
        while (j >= s && g_inc[j] > key) { g_inc[j + 1] = g_inc[j]; j--; }
        g_inc[j + 1] = key;
    }
    float deg = 2.0f;   // graph self-loop (w=1) + gcn self-loop (w=1)
    for (int i = s; i < e; i++) deg += g_ew[g_inc[i]];
    g_dinv[d] = 1.0f / sqrtf(deg);
}

// ---------------- small dense GEMM: C[N][FOUT] = A[N][FIN] @ W (+bias) ----------------
template <int FIN, int FOUT, int NB>
__global__ void gemm_kernel(const float* __restrict__ A, const float* __restrict__ W,
                            const float* __restrict__ bias, float* __restrict__ C) {
    __shared__ float As[NB][FIN];
    __shared__ float Ws[FIN * FOUT];
    const int t = threadIdx.x;        // FOUT threads
    const int n0 = blockIdx.x * NB;
    for (int i = t; i < NB * FIN; i += FOUT) As[i / FIN][i % FIN] = A[(size_t)n0 * FIN + i];
    for (int i = t; i < FIN * FOUT; i += FOUT) Ws[i] = W[i];
    __syncthreads();
#pragma unroll 1
    for (int n = 0; n < NB; n++) {
        float acc = bias ? bias[t] : 0.0f;
#pragma unroll
        for (int d = 0; d < FIN; d++) acc = fmaf(As[n][d], Ws[d * FOUT + t], acc);
        C[(size_t)(n0 + n) * FOUT + t] = acc;
    }
}

// ---------------- fused gather + bias + relu + LayerNorm (deterministic) ----------
template <int F>
__global__ void gather_epi_kernel(const float* __restrict__ h, const float* __restrict__ b,
                                  const float* __restrict__ g, const float* __restrict__ be,
                                  float* __restrict__ y) {
    const int n = blockIdx.x;
    const int f = threadIdx.x;
    __shared__ float s1[F / 32];
    __shared__ float s2[F / 32];

    int s = g_off[n], e = g_off[n + 1];
    float di = g_dinv[n];
    float acc = 0.0f;
    for (int i = s; i < e; i++) {
        int eid = g_inc[i];
        int src = eid >> 4;
        acc = fmaf(g_ew[eid] * g_dinv[src], h[(size_t)src * F + f], acc);
    }
    float v = acc * di + 2.0f * di * di * h[(size_t)n * F + f] + b[f];
    v = fmaxf(v, 0.0f);

    float sv = v;
#pragma unroll
    for (int o = 16; o; o >>= 1) sv += __shfl_xor_sync(0xffffffffu, sv, o);
    if ((f & 31) == 0) s1[f >> 5] = sv;
    __syncthreads();
    float tot = 0.0f;
#pragma unroll
    for (int i = 0; i < F / 32; i++) tot += s1[i];
    float mu = tot / (float)F;

    float dv = v - mu;
    float sq = dv * dv;
#pragma unroll
    for (int o = 16; o; o >>= 1) sq += __shfl_xor_sync(0xffffffffu, sq, o);
    if ((f & 31) == 0) s2[f >> 5] = sq;
    __syncthreads();
    float tot2 = 0.0f;
#pragma unroll
    for (int i = 0; i < F / 32; i++) tot2 += s2[i];
    float var = tot2 / (float)F;

    y[(size_t)n * F + f] = dv * (1.0f / sqrtf(var + 1e-5f)) * g[f] + be[f];
}

// ---------------- launch ----------------
extern "C" void kernel_launch(void* const* d_in, const int* in_sizes, int n_in,
                              void* d_out, int out_size) {
    const float* x   = (const float*)d_in[0];
    const float* W1  = (const float*)d_in[1];
    const float* b1  = (const float*)d_in[2];
    const float* g1  = (const float*)d_in[3];
    const float* be1 = (const float*)d_in[4];
    const float* W2  = (const float*)d_in[5];
    const float* b2  = (const float*)d_in[6];
    const float* g2  = (const float*)d_in[7];
    const float* be2 = (const float*)d_in[8];
    const float* Wp  = (const float*)d_in[9];
    const float* bp  = (const float*)d_in[10];

    float* o = (float*)d_out;
    const int OUT_ELEMS = N * D;                  // 524288
    const int E_TOTAL = E + N;                    // 139264
    const int FULL = OUT_ELEMS + 3 * E_TOTAL;     // 942080

    float* o_out = nullptr;
    float* o_ei0 = nullptr;
    float* o_ei1 = nullptr;
    float* o_ew  = nullptr;
    if (out_size >= OUT_ELEMS) o_out = o;
    if (out_size >= FULL) {
        o_ei0 = o + OUT_ELEMS;
        o_ei1 = o_ei0 + E_TOTAL;
        o_ew  = o_ei1 + E_TOTAL;
    }

    norm_init_kernel<<<(N * 32) / 256, 256>>>(x, o_ei0, o_ei1, o_ew);
    sim_kernel<<<dim3(N / 64, N / 64), 256>>>(x);
    topk_cand_kernel<<<N / 8, 256>>>(o_ei0, o_ei1, o_ew);
    fallback_kernel<<<N / 64, 256>>>(x, o_ei0, o_ei1, o_ew);

    scan_kernel<<<1, 1024>>>();
    fill_kernel<<<E / 256, 256>>>();
    sortdeg_kernel<<<(N + 255) / 256, 256>>>();

    // layer 1
    gemm_kernel<D, H1, 16><<<N / 16, H1>>>(x, W1, nullptr, g_h1);
    gather_epi_kernel<H1><<<N, H1>>>(g_h1, b1, g1, be1, g_y1);

    // layer 2
    gemm_kernel<H1, H2, 16><<<N / 16, H2>>>(g_y1, W2, nullptr, g_h2);
    gather_epi_kernel<H2><<<N, H2>>>(g_h2, b2, g2, be2, g_y2);

    // projection (+bias) straight into output
    if (o_out)
        gemm_kernel<H2, D, 16><<<N / 16, D>>>(g_y2, Wp, bp, o_out);
}